// round 14
// baseline (speedup 1.0000x reference)
#include <cuda_runtime.h>
#include <cuda_fp16.h>
#include <math.h>
#include <stdint.h>

#define BATCHN 2
#define SEQLENN 4096
#define DIMN 1024
#define DSTATE 64
#define DCONVN 4
#define DINNER 2048
#define NHEADSN 32
#define CONVD 2176          // D_INNER + 2*D_STATE
#define ZXW 4224            // z + xBC columns (dt handled separately); 33*128
#define NROWS (BATCHN*SEQLENN)   // 8192
#define NCH 64              // timesteps per chunk
#define NCHUNK (SEQLENN/NCH)    // 64
#define EPSV 1e-5f

// ------------------------- scratch -------------------------
__device__ float g_zxbcdt[(size_t)NROWS * ZXW];     // z | xBC
__device__ float g_xBCc[(size_t)NROWS * CONVD];
__device__ float g_dt[(size_t)NROWS * NHEADSN];
__device__ float g_y[(size_t)NROWS * DINNER];
__device__ float g_state[(size_t)BATCHN * NHEADSN * NCHUNK * DSTATE * 64];
__device__ float g_hin[(size_t)BATCHN * NHEADSN * NCHUNK * DSTATE * 64];
__device__ float g_acum[(size_t)BATCHN * NHEADSN * SEQLENN];

// packed fp16 operands (uint32 = 2 halves along K)
__device__ uint32_t g_Xh[(size_t)NROWS * (DIMN/2)];
__device__ uint32_t g_Wih[(size_t)ZXW * (DIMN/2)];
__device__ uint32_t g_Woh[(size_t)DIMN * (DINNER/2)];
__device__ uint32_t g_Wth[(size_t)DINNER * (DIMN/2)];
__device__ uint32_t g_ynh[(size_t)NROWS * (DINNER/2)];
__device__ uint32_t g_Hh[(size_t)NROWS * (DIMN/2)];

// ------------------------- fp16 helpers -------------------------
__device__ __forceinline__ uint32_t packh_hi(float a, float b, float& ra, float& rb) {
    __half2 h = __floats2half2_rn(a, b);
    ra = a - __half2float(__low2half(h));
    rb = b - __half2float(__high2half(h));
    return *(uint32_t*)&h;
}
__device__ __forceinline__ uint32_t packh(float a, float b) {
    __half2 h = __floats2half2_rn(a, b);
    return *(uint32_t*)&h;
}

#define MMA_F16(c, a, b) \
    asm volatile("mma.sync.aligned.m16n8k16.row.col.f32.f16.f16.f32 " \
        "{%0,%1,%2,%3}, {%4,%5,%6,%7}, {%8,%9}, {%0,%1,%2,%3};" \
        : "+f"((c)[0]), "+f"((c)[1]), "+f"((c)[2]), "+f"((c)[3]) \
        : "r"((a)[0]), "r"((a)[1]), "r"((a)[2]), "r"((a)[3]), \
          "r"((b)[0]), "r"((b)[1]))

// ------------------------- pure fp16 GEMM, double-buffered SMEM -------------------------
// 128x128 block tile, 8 warps (2x4), warp tile 64x32. One __syncthreads per K-tile.
// MODE 0: f32 C (N multiple of 128).  MODE 1: packed fp16 C.  MODE 2: f32 out with HK|HV split.
template<int MODE>
__global__ __launch_bounds__(256) void gemm_f16(
    const uint32_t* __restrict__ Ahg, const uint32_t* __restrict__ Bhg,
    float* __restrict__ Cf, uint32_t* __restrict__ Ch,
    int M, int N, int K)
{
    __shared__ uint32_t Ah[2][8][136];
    __shared__ uint32_t Bh[2][8][136];

    const int tid  = threadIdx.x;
    const int bm   = blockIdx.y * 128;
    const int bn   = blockIdx.x * 128;
    const int lane = tid & 31;
    const int warp = tid >> 5;
    const int wm   = (warp >> 2) * 64;
    const int wn   = (warp & 3) * 32;
    const int grp  = lane >> 2;
    const int qid  = lane & 3;
    const int K2   = K >> 1;
    const int nk   = K2 >> 3;

    const int sr = tid >> 1;
    const int sc = (tid & 1) * 4;
    const size_t aoff = (size_t)(bm + sr) * K2 + sc;
    const size_t boff = (size_t)(bn + sr) * K2 + sc;

    float acc[4][4][4];
#pragma unroll
    for (int i = 0; i < 4; i++)
#pragma unroll
        for (int j = 0; j < 4; j++)
#pragma unroll
            for (int e = 0; e < 4; e++) acc[i][j][e] = 0.f;

    // preload + stage tile 0 into buffer 0
    {
        uint4 a0 = *(const uint4*)(Ahg + aoff);
        uint4 b0 = *(const uint4*)(Bhg + boff);
        Ah[0][sc + 0][sr] = a0.x; Ah[0][sc + 1][sr] = a0.y;
        Ah[0][sc + 2][sr] = a0.z; Ah[0][sc + 3][sr] = a0.w;
        Bh[0][sc + 0][sr] = b0.x; Bh[0][sc + 1][sr] = b0.y;
        Bh[0][sc + 2][sr] = b0.z; Bh[0][sc + 3][sr] = b0.w;
    }
    __syncthreads();

    for (int c = 0; c < nk; c++) {
        const int cur = c & 1;
        uint4 avh, bvh;
        const bool more = (c + 1) < nk;
        if (more) {
            avh = *(const uint4*)(Ahg + aoff + (size_t)(c + 1) * 8);
            bvh = *(const uint4*)(Bhg + boff + (size_t)(c + 1) * 8);
        }

        uint32_t ah[4][4];
#pragma unroll
        for (int mf = 0; mf < 4; mf++) {
            int r0 = wm + mf * 16 + grp;
            ah[mf][0] = Ah[cur][qid    ][r0];
            ah[mf][1] = Ah[cur][qid    ][r0 + 8];
            ah[mf][2] = Ah[cur][qid + 4][r0];
            ah[mf][3] = Ah[cur][qid + 4][r0 + 8];
        }
        uint32_t bh[4][2];
#pragma unroll
        for (int nf = 0; nf < 4; nf++) {
            int c0 = wn + nf * 8 + grp;
            bh[nf][0] = Bh[cur][qid    ][c0];
            bh[nf][1] = Bh[cur][qid + 4][c0];
        }
#pragma unroll
        for (int mf = 0; mf < 4; mf++)
#pragma unroll
            for (int nf = 0; nf < 4; nf++)
                MMA_F16(acc[mf][nf], ah[mf], bh[nf]);

        if (more) {
            const int nxt = cur ^ 1;
            Ah[nxt][sc + 0][sr] = avh.x; Ah[nxt][sc + 1][sr] = avh.y;
            Ah[nxt][sc + 2][sr] = avh.z; Ah[nxt][sc + 3][sr] = avh.w;
            Bh[nxt][sc + 0][sr] = bvh.x; Bh[nxt][sc + 1][sr] = bvh.y;
            Bh[nxt][sc + 2][sr] = bvh.z; Bh[nxt][sc + 3][sr] = bvh.w;
        }
        __syncthreads();
    }

#pragma unroll
    for (int mf = 0; mf < 4; mf++) {
        int gr0 = bm + wm + mf * 16 + grp;
        int gr1 = gr0 + 8;
#pragma unroll
        for (int nf = 0; nf < 4; nf++) {
            int gc = bn + wn + nf * 8 + 2 * qid;
            if (MODE == 0) {
                Cf[(size_t)gr0 * N + gc]     = acc[mf][nf][0];
                Cf[(size_t)gr0 * N + gc + 1] = acc[mf][nf][1];
                Cf[(size_t)gr1 * N + gc]     = acc[mf][nf][2];
                Cf[(size_t)gr1 * N + gc + 1] = acc[mf][nf][3];
            } else if (MODE == 1) {
                int kp = gc >> 1;
                Ch[(size_t)gr0 * (N/2) + kp] = packh(acc[mf][nf][0], acc[mf][nf][1]);
                Ch[(size_t)gr1 * (N/2) + kp] = packh(acc[mf][nf][2], acc[mf][nf][3]);
            } else {
                size_t off = (gc < DIMN)
                    ? (size_t)gr0 * DIMN + gc
                    : (size_t)NROWS * DIMN + (size_t)gr0 * DIMN + (gc - DIMN);
                Cf[off]     = acc[mf][nf][0];
                Cf[off + 1] = acc[mf][nf][1];
                size_t off1 = off + (size_t)8 * DIMN;
                Cf[off1]     = acc[mf][nf][2];
                Cf[off1 + 1] = acc[mf][nf][3];
            }
        }
    }
}

// ------------------------- merged pack kernel (X, Wi, Wo, Wt in one launch) -------------------------
#define PN1 (NROWS * DIMN / 4)
#define PN2 (ZXW * DIMN / 4)
#define PN3 (DIMN * DINNER / 4)
#define PN4 (DINNER * DIMN / 4)
__global__ void pack_all_kernel(const float* __restrict__ X, const float* __restrict__ Wi,
                                const float* __restrict__ Wo, const float* __restrict__ Wt)
{
    int i = blockIdx.x * blockDim.x + threadIdx.x;
    const float* src;
    uint32_t* dst;
    int j = i;
    if (j < PN1) { src = X; dst = g_Xh; }
    else if ((j -= PN1) < PN2) { src = Wi; dst = g_Wih; }
    else if ((j -= PN2) < PN3) { src = Wo; dst = g_Woh; }
    else if ((j -= PN3) < PN4) { src = Wt; dst = g_Wth; }
    else return;
    float4 v = ((const float4*)src)[j];
    ((uint2*)dst)[j] = make_uint2(packh(v.x, v.y), packh(v.z, v.w));
}

// ------------------------- dt GEMV (fp32 exact) + softplus -------------------------
__global__ __launch_bounds__(256) void dt_gemv_kernel(
    const float* __restrict__ X, const float* __restrict__ Wi, const float* __restrict__ dt_bias)
{
    const int row  = blockIdx.x;
    const int tid  = threadIdx.x;
    const int warp = tid >> 5;
    const int lane = tid & 31;
    __shared__ __align__(16) float sx[DIMN];
    *(float4*)&sx[tid * 4] = *(const float4*)(X + (size_t)row * DIMN + tid * 4);
    __syncthreads();
#pragma unroll
    for (int hh = 0; hh < 4; hh++) {
        int h = warp * 4 + hh;
        const float* w = Wi + (size_t)(ZXW + h) * DIMN;
        float s = 0.f;
#pragma unroll
        for (int i = 0; i < 8; i++) {
            int k = (lane + i * 32) * 4;
            float4 xv = *(const float4*)&sx[k];
            float4 wv = *(const float4*)(w + k);
            s = fmaf(xv.x, wv.x, s); s = fmaf(xv.y, wv.y, s);
            s = fmaf(xv.z, wv.z, s); s = fmaf(xv.w, wv.w, s);
        }
        for (int o = 16; o; o >>= 1) s += __shfl_down_sync(0xffffffffu, s, o);
        if (lane == 0) {
            float v = s + dt_bias[h];
            g_dt[(size_t)row * NHEADSN + h] = (v > 20.f) ? v : log1pf(expf(v));
        }
    }
}

// ------------------------- depthwise causal conv (w=4) + bias + SiLU, tiled -------------------------
__global__ __launch_bounds__(256) void conv_silu_kernel(
    const float* __restrict__ cw, const float* __restrict__ cb)
{
    const int idx = blockIdx.x * 256 + threadIdx.x;
    const int CG = CONVD / 4;          // 544
    if (idx >= (NROWS / 4) * CG) return;
    const int cg = idx % CG;
    const int tg = idx / CG;
    const int c0 = cg * 4;
    const int l0 = (tg & (SEQLENN / 4 - 1)) * 4;
    const int b  = tg >> 10;           // SEQLENN/4 = 1024

    const float* src = g_zxbcdt + DINNER + c0;
    const float4 z4 = make_float4(0.f, 0.f, 0.f, 0.f);
    float4 in[7];
#pragma unroll
    for (int j = 0; j < 7; j++) {
        int lt = l0 + j - 3;
        in[j] = (lt >= 0) ? *(const float4*)(src + (size_t)(b * SEQLENN + lt) * ZXW) : z4;
    }
    float4 w0 = *(const float4*)(cw + (c0 + 0) * 4);
    float4 w1 = *(const float4*)(cw + (c0 + 1) * 4);
    float4 w2 = *(const float4*)(cw + (c0 + 2) * 4);
    float4 w3 = *(const float4*)(cw + (c0 + 3) * 4);
    float4 bias = *(const float4*)(cb + c0);

#pragma unroll
    for (int t = 0; t < 4; t++) {
        float ox = bias.x, oy = bias.y, oz = bias.z, ow = bias.w;
        ox = fmaf(w0.x, in[t].x, ox); ox = fmaf(w0.y, in[t+1].x, ox);
        ox = fmaf(w0.z, in[t+2].x, ox); ox = fmaf(w0.w, in[t+3].x, ox);
        oy = fmaf(w1.x, in[t].y, oy); oy = fmaf(w1.y, in[t+1].y, oy);
        oy = fmaf(w1.z, in[t+2].y, oy); oy = fmaf(w1.w, in[t+3].y, oy);
        oz = fmaf(w2.x, in[t].z, oz); oz = fmaf(w2.y, in[t+2-1].z, oz);
        oz = fmaf(w2.z, in[t+2].z, oz); oz = fmaf(w2.w, in[t+3].z, oz);
        ow = fmaf(w3.x, in[t].w, ow); ow = fmaf(w3.y, in[t+1].w, ow);
        ow = fmaf(w3.z, in[t+2].w, ow); ow = fmaf(w3.w, in[t+3].w, ow);
        float4 o;
        o.x = ox / (1.f + expf(-ox));
        o.y = oy / (1.f + expf(-oy));
        o.z = oz / (1.f + expf(-oz));
        o.w = ow / (1.f + expf(-ow));
        *(float4*)(g_xBCc + (size_t)(b * SEQLENN + l0 + t) * CONVD + c0) = o;
    }
}

// ------------------------- pass A: chunked SSD scan via MMA -------------------------
__global__ __launch_bounds__(128) void scan_chunk_kernel(const float* __restrict__ A_log)
{
    const int bid   = blockIdx.x;
    const int chunk = bid & (NCHUNK - 1);
    const int h     = (bid >> 6) & (NHEADSN - 1);
    const int b     = bid >> 11;
    const int tid   = threadIdx.x;
    const int warp  = tid >> 5;
    const int lane  = tid & 31;
    const int grp   = lane >> 2;
    const int qid   = lane & 3;
    const float Ahc = -expf(A_log[h]);
    const int bh    = b * NHEADSN + h;
    const int rbase = b * SEQLENN + chunk * NCH;
    const int r0    = warp * 16 + grp;
    const int r1    = r0 + 8;

    __shared__ uint32_t b1h[32][72];
    __shared__ uint32_t b1l[32][72];
    __shared__ uint32_t b2[32][72];
    __shared__ uint32_t b3[32][72];
    __shared__ float sdt[NCH], scum[NCH], seL[NCH];

    if (tid < NCH) sdt[tid] = g_dt[(size_t)(rbase + tid) * NHEADSN + h];
#pragma unroll
    for (int it = 0; it < 8; it++) {
        int idx = tid + it * 128;
        int r   = idx >> 4;
        int kk  = (idx & 15) << 2;
        size_t ro = (size_t)(rbase + r) * CONVD + DINNER;
        float4 bv = *(const float4*)(g_xBCc + ro + kk);
        float4 cv = *(const float4*)(g_xBCc + ro + DSTATE + kk);
        int sp = kk >> 1;
        float e0, e1;
        b1h[sp    ][r] = packh_hi(cv.x, cv.y, e0, e1); b1l[sp    ][r] = packh(e0, e1);
        b1h[sp + 1][r] = packh_hi(cv.z, cv.w, e0, e1); b1l[sp + 1][r] = packh(e0, e1);
        b2[sp    ][r] = packh(bv.x, bv.y);
        b2[sp + 1][r] = packh(bv.z, bv.w);
    }
    __syncthreads();
    if (tid == 0) {
        float c = 0.f;
#pragma unroll
        for (int t = 0; t < NCH; t++) { c += sdt[t] * Ahc; scum[t] = c; }
    }
    __syncthreads();
    if (tid < NCH) {
        seL[tid] = __expf(scum[NCH - 1] - scum[tid]);
        g_acum[(size_t)bh * SEQLENN + chunk * NCH + tid] = __expf(scum[tid]);
    }
#pragma unroll
    for (int it = 0; it < 16; it++) {
        int idx = tid + it * 128;
        int kp  = idx >> 6;
        int p   = idx & 63;
        size_t ro = (size_t)(rbase + 2 * kp) * CONVD + h * 64 + p;
        float x0 = g_xBCc[ro]          * sdt[2 * kp];
        float x1 = g_xBCc[ro + CONVD]  * sdt[2 * kp + 1];
        b3[kp][p] = packh(x0, x1);
    }
    __syncthreads();

    float gacc[8][4];
#pragma unroll
    for (int i = 0; i < 8; i++)
#pragma unroll
        for (int e = 0; e < 4; e++) gacc[i][e] = 0.f;
#pragma unroll
    for (int ks = 0; ks < 4; ks++) {
        uint32_t ah[4], al[4];
        ah[0] = b1h[ks*8+qid  ][r0]; ah[1] = b1h[ks*8+qid  ][r1];
        ah[2] = b1h[ks*8+qid+4][r0]; ah[3] = b1h[ks*8+qid+4][r1];
        al[0] = b1l[ks*8+qid  ][r0]; al[1] = b1l[ks*8+qid  ][r1];
        al[2] = b1l[ks*8+qid+4][r0]; al[3] = b1l[ks*8+qid+4][r1];
#pragma unroll
        for (int nf = 0; nf < 8; nf++) {
            int c0 = nf * 8 + grp;
            uint32_t bb[2] = { b2[ks*8+qid][c0], b2[ks*8+qid+4][c0] };
            MMA_F16(gacc[nf], ah, bb);
            MMA_F16(gacc[nf], al, bb);
        }
    }
    __syncthreads();

#pragma unroll
    for (int nf = 0; nf < 8; nf++) {
        int s0 = nf * 8 + 2 * qid;
        float m0 = (s0     <= r0) ? gacc[nf][0] * __expf(scum[r0] - scum[s0    ]) : 0.f;
        float m1 = (s0 + 1 <= r0) ? gacc[nf][1] * __expf(scum[r0] - scum[s0 + 1]) : 0.f;
        float m2 = (s0     <= r1) ? gacc[nf][2] * __expf(scum[r1] - scum[s0    ]) : 0.f;
        float m3 = (s0 + 1 <= r1) ? gacc[nf][3] * __expf(scum[r1] - scum[s0 + 1]) : 0.f;
        int kp = nf * 4 + qid;
        float e0, e1;
        uint32_t h0 = packh_hi(m0, m1, e0, e1); uint32_t l0 = packh(e0, e1);
        uint32_t h1 = packh_hi(m2, m3, e0, e1); uint32_t l1 = packh(e0, e1);
        b1h[kp][r0] = h0; b1l[kp][r0] = l0;
        b1h[kp][r1] = h1; b1l[kp][r1] = l1;
    }
#pragma unroll
    for (int it = 0; it < 16; it++) {
        int idx = tid + it * 128;
        int kp  = idx >> 6;
        int n   = idx & 63;
        size_t ro = (size_t)(rbase + 2 * kp) * CONVD + DINNER + n;
        float v0 = g_xBCc[ro]         * seL[2 * kp];
        float v1 = g_xBCc[ro + CONVD] * seL[2 * kp + 1];
        b2[kp][n] = packh(v0, v1);
    }
    __syncthreads();

    float yacc[8][4], sacc[8][4];
#pragma unroll
    for (int i = 0; i < 8; i++)
#pragma unroll
        for (int e = 0; e < 4; e++) { yacc[i][e] = 0.f; sacc[i][e] = 0.f; }
#pragma unroll
    for (int ks = 0; ks < 4; ks++) {
        uint32_t mh[4], ml[4], sh[4];
        mh[0] = b1h[ks*8+qid  ][r0]; mh[1] = b1h[ks*8+qid  ][r1];
        mh[2] = b1h[ks*8+qid+4][r0]; mh[3] = b1h[ks*8+qid+4][r1];
        ml[0] = b1l[ks*8+qid  ][r0]; ml[1] = b1l[ks*8+qid  ][r1];
        ml[2] = b1l[ks*8+qid+4][r0]; ml[3] = b1l[ks*8+qid+4][r1];
        sh[0] = b2[ks*8+qid  ][r0];  sh[1] = b2[ks*8+qid  ][r1];
        sh[2] = b2[ks*8+qid+4][r0];  sh[3] = b2[ks*8+qid+4][r1];
#pragma unroll
        for (int nf = 0; nf < 8; nf++) {
            int c0 = nf * 8 + grp;
            uint32_t bb[2] = { b3[ks*8+qid][c0], b3[ks*8+qid+4][c0] };
            MMA_F16(yacc[nf], mh, bb);
            MMA_F16(yacc[nf], ml, bb);
            MMA_F16(sacc[nf], sh, bb);
        }
    }

    const size_t sbase = (size_t)(bh * NCHUNK + chunk) * (64 * DSTATE);
#pragma unroll
    for (int nf = 0; nf < 8; nf++) {
        int p0 = nf * 8 + 2 * qid;
        size_t y0 = (size_t)(rbase + r0) * DINNER + h * 64 + p0;
        size_t y1 = (size_t)(rbase + r1) * DINNER + h * 64 + p0;
        g_y[y0]     = yacc[nf][0];
        g_y[y0 + 1] = yacc[nf][1];
        g_y[y1]     = yacc[nf][2];
        g_y[y1 + 1] = yacc[nf][3];
        g_state[sbase + (size_t)r0 * 64 + p0]     = sacc[nf][0];
        g_state[sbase + (size_t)r0 * 64 + p0 + 1] = sacc[nf][1];
        g_state[sbase + (size_t)r1 * 64 + p0]     = sacc[nf][2];
        g_state[sbase + (size_t)r1 * 64 + p0 + 1] = sacc[nf][3];
    }
}

// ------------------------- pass B: prefix over chunk states -------------------------
__global__ __launch_bounds__(256) void state_combine_kernel()
{
    const int bh = blockIdx.x;
    const int tid = threadIdx.x;
    const size_t base = (size_t)bh * NCHUNK * (64 * DSTATE);
    float4 hin[4];
#pragma unroll
    for (int q = 0; q < 4; q++) hin[q] = make_float4(0.f, 0.f, 0.f, 0.f);

    for (int c = 1; c < NCHUNK; c++) {
        float ap = g_acum[(size_t)bh * SEQLENN + c * NCH - 1];
        const float4* sl = (const float4*)(g_state + base + (size_t)(c - 1) * (64 * DSTATE) + tid * 16);
        float4* ho = (float4*)(g_hin + base + (size_t)c * (64 * DSTATE) + tid * 16);
#pragma unroll
        for (int q = 0; q < 4; q++) {
            float4 s = sl[q];
            hin[q].x = fmaf(hin[q].x, ap, s.x);
            hin[q].y = fmaf(hin[q].y, ap, s.y);
            hin[q].z = fmaf(hin[q].z, ap, s.z);
            hin[q].w = fmaf(hin[q].w, ap, s.w);
            ho[q] = hin[q];
        }
    }
}

// ------------------------- pass C: y += (C .* L) @ S_in^T -------------------------
__global__ __launch_bounds__(128) void carry_mma_kernel()
{
    const int bid   = blockIdx.x;
    const int chunk = 1 + (bid % (NCHUNK - 1));
    const int bh    = bid / (NCHUNK - 1);
    const int h     = bh & (NHEADSN - 1);
    const int b     = bh >> 5;
    const int tid   = threadIdx.x;
    const int warp  = tid >> 5;
    const int lane  = tid & 31;
    const int grp   = lane >> 2;
    const int qid   = lane & 3;
    const int rbase = b * SEQLENN + chunk * NCH;
    const int r0    = warp * 16 + grp;
    const int r1    = r0 + 8;

    __shared__ uint32_t ach[32][72];
    __shared__ uint32_t acl[32][72];
    __shared__ uint32_t sbb[32][72];

#pragma unroll
    for (int it = 0; it < 8; it++) {
        int idx = tid + it * 128;
        int r   = idx >> 4;
        int kk  = (idx & 15) << 2;
        float Lt = g_acum[(size_t)bh * SEQLENN + chunk * NCH + r];
        float4 cv = *(const float4*)(g_xBCc + (size_t)(rbase + r) * CONVD + DINNER + DSTATE + kk);
        cv.x *= Lt; cv.y *= Lt; cv.z *= Lt; cv.w *= Lt;
        int sp = kk >> 1;
        float e0, e1;
        ach[sp    ][r] = packh_hi(cv.x, cv.y, e0, e1); acl[sp    ][r] = packh(e0, e1);
        ach[sp + 1][r] = packh_hi(cv.z, cv.w, e0, e1); acl[sp + 1][r] = packh(e0, e1);
    }
    {
        const float* si = g_hin + (size_t)(bh * NCHUNK + chunk) * (64 * DSTATE);
#pragma unroll
        for (int it = 0; it < 16; it++) {
            int idx = tid + it * 128;
            int kp  = idx >> 6;
            int p   = idx & 63;
            float s0 = si[(size_t)(2 * kp) * 64 + p];
            float s1 = si[(size_t)(2 * kp + 1) * 64 + p];
            sbb[kp][p] = packh(s0, s1);
        }
    }
    __syncthreads();

    float yacc[8][4];
#pragma unroll
    for (int i = 0; i < 8; i++)
#pragma unroll
        for (int e = 0; e < 4; e++) yacc[i][e] = 0.f;
#pragma unroll
    for (int ks = 0; ks < 4; ks++) {
        uint32_t ah[4], al[4];
        ah[0] = ach[ks*8+qid  ][r0]; ah[1] = ach[ks*8+qid  ][r1];
        ah[2] = ach[ks*8+qid+4][r0]; ah[3] = ach[ks*8+qid+4][r1];
        al[0] = acl[ks*8+qid  ][r0]; al[1] = acl[ks*8+qid  ][r1];
        al[2] = acl[ks*8+qid+4][r0]; al[3] = acl[ks*8+qid+4][r1];
#pragma unroll
        for (int nf = 0; nf < 8; nf++) {
            int c0 = nf * 8 + grp;
            uint32_t bb[2] = { sbb[ks*8+qid][c0], sbb[ks*8+qid+4][c0] };
            MMA_F16(yacc[nf], ah, bb);
            MMA_F16(yacc[nf], al, bb);
        }
    }

#pragma unroll
    for (int nf = 0; nf < 8; nf++) {
        int p0 = nf * 8 + 2 * qid;
        size_t y0 = (size_t)(rbase + r0) * DINNER + h * 64 + p0;
        size_t y1 = (size_t)(rbase + r1) * DINNER + h * 64 + p0;
        g_y[y0]     += yacc[nf][0];
        g_y[y0 + 1] += yacc[nf][1];
        g_y[y1]     += yacc[nf][2];
        g_y[y1 + 1] += yacc[nf][3];
    }
}

// ------------------------- D*x, gate, RMSNorm -> packed fp16 -------------------------
__global__ __launch_bounds__(256) void gate_norm_kernel(
    const float* __restrict__ Dp, const float* __restrict__ norm_w)
{
    const int row = blockIdx.x;
    const int tid = threadIdx.x;
    const int c0 = tid * 8;
    const int hh = c0 >> 6;

    float vals[8];
    float ss = 0.f;
    {
        const float4* yv = (const float4*)(g_y + (size_t)row * DINNER + c0);
        const float4* xv = (const float4*)(g_xBCc + (size_t)row * CONVD + c0);
        const float4* zv = (const float4*)(g_zxbcdt + (size_t)row * ZXW + c0);
        float Dh = Dp[hh];
#pragma unroll
        for (int q = 0; q < 2; q++) {
            float4 y = yv[q], x = xv[q], z = zv[q];
            float a[4] = {y.x, y.y, y.z, y.w};
            float bb[4] = {x.x, x.y, x.z, x.w};
            float g[4] = {z.x, z.y, z.z, z.w};
#pragma unroll
            for (int e = 0; e < 4; e++) {
                float yy = fmaf(Dh, bb[e], a[e]);
                float gg = g[e] / (1.f + expf(-g[e]));
                float v = yy * gg;
                vals[q * 4 + e] = v;
                ss = fmaf(v, v, ss);
            }
        }
    }
    __shared__ float red[32];
    for (int o = 16; o; o >>= 1) ss += __shfl_down_sync(0xffffffffu, ss, o);
    if ((tid & 31) == 0) red[tid >> 5] = ss;
    __syncthreads();
    if (tid < 32) {
        float s2 = (tid < 8) ? red[tid] : 0.f;
        for (int o = 4; o; o >>= 1) s2 += __shfl_down_sync(0xffffffffu, s2, o);
        if (tid == 0) red[0] = s2;
    }
    __syncthreads();
    float scale = rsqrtf(red[0] / (float)DINNER + EPSV);

    uint32_t ho[4];
#pragma unroll
    for (int j = 0; j < 4; j++) {
        float a  = vals[2*j]     * scale * norm_w[c0 + 2*j];
        float bv = vals[2*j + 1] * scale * norm_w[c0 + 2*j + 1];
        ho[j] = packh(a, bv);
    }
    *(uint4*)(g_ynh + (size_t)row * (DINNER/2) + tid * 4) = *(uint4*)ho;
}

// ------------------------- launch -------------------------
extern "C" void kernel_launch(void* const* d_in, const int* in_sizes, int n_in,
                              void* d_out, int out_size)
{
    const float* X          = (const float*)d_in[0];
    const float* in_proj_w  = (const float*)d_in[1];
    const float* conv_w     = (const float*)d_in[2];
    const float* conv_b     = (const float*)d_in[3];
    const float* dt_bias    = (const float*)d_in[4];
    const float* A_log      = (const float*)d_in[5];
    const float* Dp         = (const float*)d_in[6];
    const float* norm_w     = (const float*)d_in[7];
    const float* out_proj_w = (const float*)d_in[8];
    const float* to_h_w     = (const float*)d_in[9];
    float* out = (float*)d_out;

    float *zx;
    uint32_t *Xh, *Wih, *Woh, *Wth, *ynh, *Hh;
    cudaGetSymbolAddress((void**)&zx,  g_zxbcdt);
    cudaGetSymbolAddress((void**)&Xh,  g_Xh);
    cudaGetSymbolAddress((void**)&Wih, g_Wih);
    cudaGetSymbolAddress((void**)&Woh, g_Woh);
    cudaGetSymbolAddress((void**)&Wth, g_Wth);
    cudaGetSymbolAddress((void**)&ynh, g_ynh);
    cudaGetSymbolAddress((void**)&Hh,  g_Hh);

    // 0) pack all operands to fp16 (single launch)
    pack_all_kernel<<<(PN1 + PN2 + PN3 + PN4 + 255) / 256, 256>>>(X, in_proj_w, out_proj_w, to_h_w);

    // 1) z|xBC = X @ in_proj_w[0:4224]^T  (pure fp16, double-buffered)
    gemm_f16<0><<<dim3(ZXW / 128, NROWS / 128), 256>>>(
        Xh, Wih, zx, nullptr, NROWS, ZXW, DIMN);
    // 2) dt = softplus(X . Wi_dt + bias)  (fp32 exact)
    dt_gemv_kernel<<<NROWS, 256>>>(X, in_proj_w, dt_bias);
    // 3) conv + silu (tiled)
    conv_silu_kernel<<<((NROWS / 4) * (CONVD / 4) + 255) / 256, 256>>>(conv_w, conv_b);
    // 4) chunked SSD scan: local MMA pass, state prefix, carry MMA
    scan_chunk_kernel<<<BATCHN * NHEADSN * NCHUNK, 128>>>(A_log);
    state_combine_kernel<<<BATCHN * NHEADSN, 256>>>();
    carry_mma_kernel<<<BATCHN * NHEADSN * (NCHUNK - 1), 128>>>();
    // 5) gate + rmsnorm -> packed fp16 yn
    gate_norm_kernel<<<NROWS, 256>>>(Dp, norm_w);
    // 6) H = yn @ out_proj_w^T  (pure fp16, packed out)
    gemm_f16<1><<<dim3(DIMN / 128, NROWS / 128), 256>>>(
        ynh, Woh, nullptr, Hh, NROWS, DIMN, DINNER);
    // 7) HKV = H @ to_h_w^T with fused split  (pure fp16)
    gemm_f16<2><<<dim3(DINNER / 128, NROWS / 128), 256>>>(
        Hh, Wth, out, nullptr, NROWS, DINNER, DIMN);
}

// round 15
// speedup vs baseline: 1.0416x; 1.0416x over previous
#include <cuda_runtime.h>
#include <cuda_fp16.h>
#include <math.h>
#include <stdint.h>

#define BATCHN 2
#define SEQLENN 4096
#define DIMN 1024
#define DSTATE 64
#define DCONVN 4
#define DINNER 2048
#define NHEADSN 32
#define CONVD 2176          // D_INNER + 2*D_STATE
#define ZXW 4224            // z + xBC columns (dt handled separately); 33*128
#define NROWS (BATCHN*SEQLENN)   // 8192
#define NCH 64              // timesteps per chunk
#define NCHUNK (SEQLENN/NCH)    // 64
#define EPSV 1e-5f

// ------------------------- scratch -------------------------
__device__ float g_zxbcdt[(size_t)NROWS * ZXW];     // z | xBC
__device__ float g_xBCc[(size_t)NROWS * CONVD];
__device__ float g_dt[(size_t)NROWS * NHEADSN];
__device__ float g_y[(size_t)NROWS * DINNER];
__device__ float g_state[(size_t)BATCHN * NHEADSN * NCHUNK * DSTATE * 64];
__device__ float g_hin[(size_t)BATCHN * NHEADSN * NCHUNK * DSTATE * 64];
__device__ float g_acum[(size_t)BATCHN * NHEADSN * SEQLENN];

// packed fp16 operands (uint32 = 2 halves along K)
__device__ uint32_t g_Xh[(size_t)NROWS * (DIMN/2)];
__device__ uint32_t g_Wih[(size_t)ZXW * (DIMN/2)];
__device__ uint32_t g_Woh[(size_t)DIMN * (DINNER/2)];
__device__ uint32_t g_Wth[(size_t)DINNER * (DIMN/2)];
__device__ uint32_t g_ynh[(size_t)NROWS * (DINNER/2)];
__device__ uint32_t g_Hh[(size_t)NROWS * (DIMN/2)];

// ------------------------- fp16 helpers -------------------------
__device__ __forceinline__ uint32_t packh_hi(float a, float b, float& ra, float& rb) {
    __half2 h = __floats2half2_rn(a, b);
    ra = a - __half2float(__low2half(h));
    rb = b - __half2float(__high2half(h));
    return *(uint32_t*)&h;
}
__device__ __forceinline__ uint32_t packh(float a, float b) {
    __half2 h = __floats2half2_rn(a, b);
    return *(uint32_t*)&h;
}

#define MMA_F16(c, a, b) \
    asm volatile("mma.sync.aligned.m16n8k16.row.col.f32.f16.f16.f32 " \
        "{%0,%1,%2,%3}, {%4,%5,%6,%7}, {%8,%9}, {%0,%1,%2,%3};" \
        : "+f"((c)[0]), "+f"((c)[1]), "+f"((c)[2]), "+f"((c)[3]) \
        : "r"((a)[0]), "r"((a)[1]), "r"((a)[2]), "r"((a)[3]), \
          "r"((b)[0]), "r"((b)[1]))

// ------------------------- pure fp16 GEMM: C[M,N] = Ah[M,K] @ Bh[N,K]^T (R11/R13-proven) -------------------------
// 128x128 block tile, 8 warps (2x4), warp tile 64x32.
// MODE 0: f32 C (N multiple of 128).  MODE 1: packed fp16 C.  MODE 2: f32 out with HK|HV split.
template<int MODE>
__global__ __launch_bounds__(256) void gemm_f16(
    const uint32_t* __restrict__ Ahg, const uint32_t* __restrict__ Bhg,
    float* __restrict__ Cf, uint32_t* __restrict__ Ch,
    int M, int N, int K)
{
    __shared__ uint32_t Ah[8][136];
    __shared__ uint32_t Bh[8][136];

    const int tid  = threadIdx.x;
    const int bm   = blockIdx.y * 128;
    const int bn   = blockIdx.x * 128;
    const int lane = tid & 31;
    const int warp = tid >> 5;
    const int wm   = (warp >> 2) * 64;
    const int wn   = (warp & 3) * 32;
    const int grp  = lane >> 2;
    const int qid  = lane & 3;
    const int K2   = K >> 1;

    const int sr = tid >> 1;
    const int sc = (tid & 1) * 4;
    const size_t aoff = (size_t)(bm + sr) * K2 + sc;
    const size_t boff = (size_t)(bn + sr) * K2 + sc;

    float acc[4][4][4];
#pragma unroll
    for (int i = 0; i < 4; i++)
#pragma unroll
        for (int j = 0; j < 4; j++)
#pragma unroll
            for (int e = 0; e < 4; e++) acc[i][j][e] = 0.f;

    uint4 avh = *(const uint4*)(Ahg + aoff);
    uint4 bvh = *(const uint4*)(Bhg + boff);

    for (int kb = 0; kb < K2; kb += 8) {
        Ah[sc + 0][sr] = avh.x; Ah[sc + 1][sr] = avh.y;
        Ah[sc + 2][sr] = avh.z; Ah[sc + 3][sr] = avh.w;
        Bh[sc + 0][sr] = bvh.x; Bh[sc + 1][sr] = bvh.y;
        Bh[sc + 2][sr] = bvh.z; Bh[sc + 3][sr] = bvh.w;
        __syncthreads();

        if (kb + 8 < K2) {
            avh = *(const uint4*)(Ahg + aoff + kb + 8);
            bvh = *(const uint4*)(Bhg + boff + kb + 8);
        }

        uint32_t ah[4][4];
#pragma unroll
        for (int mf = 0; mf < 4; mf++) {
            int r0 = wm + mf * 16 + grp;
            ah[mf][0] = Ah[qid    ][r0];
            ah[mf][1] = Ah[qid    ][r0 + 8];
            ah[mf][2] = Ah[qid + 4][r0];
            ah[mf][3] = Ah[qid + 4][r0 + 8];
        }
        uint32_t bh[4][2];
#pragma unroll
        for (int nf = 0; nf < 4; nf++) {
            int c0 = wn + nf * 8 + grp;
            bh[nf][0] = Bh[qid    ][c0];
            bh[nf][1] = Bh[qid + 4][c0];
        }
#pragma unroll
        for (int mf = 0; mf < 4; mf++)
#pragma unroll
            for (int nf = 0; nf < 4; nf++)
                MMA_F16(acc[mf][nf], ah[mf], bh[nf]);
        __syncthreads();
    }

#pragma unroll
    for (int mf = 0; mf < 4; mf++) {
        int gr0 = bm + wm + mf * 16 + grp;
        int gr1 = gr0 + 8;
#pragma unroll
        for (int nf = 0; nf < 4; nf++) {
            int gc = bn + wn + nf * 8 + 2 * qid;
            if (MODE == 0) {
                Cf[(size_t)gr0 * N + gc]     = acc[mf][nf][0];
                Cf[(size_t)gr0 * N + gc + 1] = acc[mf][nf][1];
                Cf[(size_t)gr1 * N + gc]     = acc[mf][nf][2];
                Cf[(size_t)gr1 * N + gc + 1] = acc[mf][nf][3];
            } else if (MODE == 1) {
                int kp = gc >> 1;
                Ch[(size_t)gr0 * (N/2) + kp] = packh(acc[mf][nf][0], acc[mf][nf][1]);
                Ch[(size_t)gr1 * (N/2) + kp] = packh(acc[mf][nf][2], acc[mf][nf][3]);
            } else {
                size_t off = (gc < DIMN)
                    ? (size_t)gr0 * DIMN + gc
                    : (size_t)NROWS * DIMN + (size_t)gr0 * DIMN + (gc - DIMN);
                Cf[off]     = acc[mf][nf][0];
                Cf[off + 1] = acc[mf][nf][1];
                size_t off1 = off + (size_t)8 * DIMN;
                Cf[off1]     = acc[mf][nf][2];
                Cf[off1 + 1] = acc[mf][nf][3];
            }
        }
    }
}

// ------------------------- merged pack kernel (X, Wi, Wo, Wt in one launch) -------------------------
#define PN1 (NROWS * DIMN / 4)
#define PN2 (ZXW * DIMN / 4)
#define PN3 (DIMN * DINNER / 4)
#define PN4 (DINNER * DIMN / 4)
__global__ void pack_all_kernel(const float* __restrict__ X, const float* __restrict__ Wi,
                                const float* __restrict__ Wo, const float* __restrict__ Wt)
{
    int i = blockIdx.x * blockDim.x + threadIdx.x;
    const float* src;
    uint32_t* dst;
    int j = i;
    if (j < PN1) { src = X; dst = g_Xh; }
    else if ((j -= PN1) < PN2) { src = Wi; dst = g_Wih; }
    else if ((j -= PN2) < PN3) { src = Wo; dst = g_Woh; }
    else if ((j -= PN3) < PN4) { src = Wt; dst = g_Wth; }
    else return;
    float4 v = ((const float4*)src)[j];
    ((uint2*)dst)[j] = make_uint2(packh(v.x, v.y), packh(v.z, v.w));
}

// ------------------------- dt GEMV (fp32 exact) + softplus -------------------------
__global__ __launch_bounds__(256) void dt_gemv_kernel(
    const float* __restrict__ X, const float* __restrict__ Wi, const float* __restrict__ dt_bias)
{
    const int row  = blockIdx.x;
    const int tid  = threadIdx.x;
    const int warp = tid >> 5;
    const int lane = tid & 31;
    __shared__ __align__(16) float sx[DIMN];
    *(float4*)&sx[tid * 4] = *(const float4*)(X + (size_t)row * DIMN + tid * 4);
    __syncthreads();
#pragma unroll
    for (int hh = 0; hh < 4; hh++) {
        int h = warp * 4 + hh;
        const float* w = Wi + (size_t)(ZXW + h) * DIMN;
        float s = 0.f;
#pragma unroll
        for (int i = 0; i < 8; i++) {
            int k = (lane + i * 32) * 4;
            float4 xv = *(const float4*)&sx[k];
            float4 wv = *(const float4*)(w + k);
            s = fmaf(xv.x, wv.x, s); s = fmaf(xv.y, wv.y, s);
            s = fmaf(xv.z, wv.z, s); s = fmaf(xv.w, wv.w, s);
        }
        for (int o = 16; o; o >>= 1) s += __shfl_down_sync(0xffffffffu, s, o);
        if (lane == 0) {
            float v = s + dt_bias[h];
            g_dt[(size_t)row * NHEADSN + h] = (v > 20.f) ? v : log1pf(expf(v));
        }
    }
}

// ------------------------- depthwise causal conv (w=4) + bias + SiLU, tiled -------------------------
__global__ __launch_bounds__(256) void conv_silu_kernel(
    const float* __restrict__ cw, const float* __restrict__ cb)
{
    const int idx = blockIdx.x * 256 + threadIdx.x;
    const int CG = CONVD / 4;          // 544
    if (idx >= (NROWS / 4) * CG) return;
    const int cg = idx % CG;
    const int tg = idx / CG;
    const int c0 = cg * 4;
    const int l0 = (tg & (SEQLENN / 4 - 1)) * 4;
    const int b  = tg >> 10;           // SEQLENN/4 = 1024

    const float* src = g_zxbcdt + DINNER + c0;
    const float4 z4 = make_float4(0.f, 0.f, 0.f, 0.f);
    float4 in[7];
#pragma unroll
    for (int j = 0; j < 7; j++) {
        int lt = l0 + j - 3;
        in[j] = (lt >= 0) ? *(const float4*)(src + (size_t)(b * SEQLENN + lt) * ZXW) : z4;
    }
    float4 w0 = *(const float4*)(cw + (c0 + 0) * 4);
    float4 w1 = *(const float4*)(cw + (c0 + 1) * 4);
    float4 w2 = *(const float4*)(cw + (c0 + 2) * 4);
    float4 w3 = *(const float4*)(cw + (c0 + 3) * 4);
    float4 bias = *(const float4*)(cb + c0);

#pragma unroll
    for (int t = 0; t < 4; t++) {
        float ox = bias.x, oy = bias.y, oz = bias.z, ow = bias.w;
        ox = fmaf(w0.x, in[t].x, ox); ox = fmaf(w0.y, in[t+1].x, ox);
        ox = fmaf(w0.z, in[t+2].x, ox); ox = fmaf(w0.w, in[t+3].x, ox);
        oy = fmaf(w1.x, in[t].y, oy); oy = fmaf(w1.y, in[t+1].y, oy);
        oy = fmaf(w1.z, in[t+2].y, oy); oy = fmaf(w1.w, in[t+3].y, oy);
        oz = fmaf(w2.x, in[t].z, oz); oz = fmaf(w2.y, in[t+1].z, oz);
        oz = fmaf(w2.z, in[t+2].z, oz); oz = fmaf(w2.w, in[t+3].z, oz);
        ow = fmaf(w3.x, in[t].w, ow); ow = fmaf(w3.y, in[t+1].w, ow);
        ow = fmaf(w3.z, in[t+2].w, ow); ow = fmaf(w3.w, in[t+3].w, ow);
        float4 o;
        o.x = ox / (1.f + expf(-ox));
        o.y = oy / (1.f + expf(-oy));
        o.z = oz / (1.f + expf(-oz));
        o.w = ow / (1.f + expf(-ow));
        *(float4*)(g_xBCc + (size_t)(b * SEQLENN + l0 + t) * CONVD + c0) = o;
    }
}

// ------------------------- pass A: chunked SSD scan via MMA -------------------------
__global__ __launch_bounds__(128) void scan_chunk_kernel(const float* __restrict__ A_log)
{
    const int bid   = blockIdx.x;
    const int chunk = bid & (NCHUNK - 1);
    const int h     = (bid >> 6) & (NHEADSN - 1);
    const int b     = bid >> 11;
    const int tid   = threadIdx.x;
    const int warp  = tid >> 5;
    const int lane  = tid & 31;
    const int grp   = lane >> 2;
    const int qid   = lane & 3;
    const float Ahc = -expf(A_log[h]);
    const int bh    = b * NHEADSN + h;
    const int rbase = b * SEQLENN + chunk * NCH;
    const int r0    = warp * 16 + grp;
    const int r1    = r0 + 8;

    __shared__ uint32_t b1h[32][72];
    __shared__ uint32_t b1l[32][72];
    __shared__ uint32_t b2[32][72];
    __shared__ uint32_t b3[32][72];
    __shared__ float sdt[NCH], scum[NCH], seL[NCH];

    if (tid < NCH) sdt[tid] = g_dt[(size_t)(rbase + tid) * NHEADSN + h];
#pragma unroll
    for (int it = 0; it < 8; it++) {
        int idx = tid + it * 128;
        int r   = idx >> 4;
        int kk  = (idx & 15) << 2;
        size_t ro = (size_t)(rbase + r) * CONVD + DINNER;
        float4 bv = *(const float4*)(g_xBCc + ro + kk);
        float4 cv = *(const float4*)(g_xBCc + ro + DSTATE + kk);
        int sp = kk >> 1;
        float e0, e1;
        b1h[sp    ][r] = packh_hi(cv.x, cv.y, e0, e1); b1l[sp    ][r] = packh(e0, e1);
        b1h[sp + 1][r] = packh_hi(cv.z, cv.w, e0, e1); b1l[sp + 1][r] = packh(e0, e1);
        b2[sp    ][r] = packh(bv.x, bv.y);
        b2[sp + 1][r] = packh(bv.z, bv.w);
    }
    __syncthreads();
    if (tid == 0) {
        float c = 0.f;
#pragma unroll
        for (int t = 0; t < NCH; t++) { c += sdt[t] * Ahc; scum[t] = c; }
    }
    __syncthreads();
    if (tid < NCH) {
        seL[tid] = __expf(scum[NCH - 1] - scum[tid]);
        g_acum[(size_t)bh * SEQLENN + chunk * NCH + tid] = __expf(scum[tid]);
    }
#pragma unroll
    for (int it = 0; it < 16; it++) {
        int idx = tid + it * 128;
        int kp  = idx >> 6;
        int p   = idx & 63;
        size_t ro = (size_t)(rbase + 2 * kp) * CONVD + h * 64 + p;
        float x0 = g_xBCc[ro]          * sdt[2 * kp];
        float x1 = g_xBCc[ro + CONVD]  * sdt[2 * kp + 1];
        b3[kp][p] = packh(x0, x1);
    }
    __syncthreads();

    float gacc[8][4];
#pragma unroll
    for (int i = 0; i < 8; i++)
#pragma unroll
        for (int e = 0; e < 4; e++) gacc[i][e] = 0.f;
#pragma unroll
    for (int ks = 0; ks < 4; ks++) {
        uint32_t ah[4], al[4];
        ah[0] = b1h[ks*8+qid  ][r0]; ah[1] = b1h[ks*8+qid  ][r1];
        ah[2] = b1h[ks*8+qid+4][r0]; ah[3] = b1h[ks*8+qid+4][r1];
        al[0] = b1l[ks*8+qid  ][r0]; al[1] = b1l[ks*8+qid  ][r1];
        al[2] = b1l[ks*8+qid+4][r0]; al[3] = b1l[ks*8+qid+4][r1];
#pragma unroll
        for (int nf = 0; nf < 8; nf++) {
            int c0 = nf * 8 + grp;
            uint32_t bb[2] = { b2[ks*8+qid][c0], b2[ks*8+qid+4][c0] };
            MMA_F16(gacc[nf], ah, bb);
            MMA_F16(gacc[nf], al, bb);
        }
    }
    __syncthreads();

#pragma unroll
    for (int nf = 0; nf < 8; nf++) {
        int s0 = nf * 8 + 2 * qid;
        float m0 = (s0     <= r0) ? gacc[nf][0] * __expf(scum[r0] - scum[s0    ]) : 0.f;
        float m1 = (s0 + 1 <= r0) ? gacc[nf][1] * __expf(scum[r0] - scum[s0 + 1]) : 0.f;
        float m2 = (s0     <= r1) ? gacc[nf][2] * __expf(scum[r1] - scum[s0    ]) : 0.f;
        float m3 = (s0 + 1 <= r1) ? gacc[nf][3] * __expf(scum[r1] - scum[s0 + 1]) : 0.f;
        int kp = nf * 4 + qid;
        float e0, e1;
        uint32_t h0 = packh_hi(m0, m1, e0, e1); uint32_t l0 = packh(e0, e1);
        uint32_t h1 = packh_hi(m2, m3, e0, e1); uint32_t l1 = packh(e0, e1);
        b1h[kp][r0] = h0; b1l[kp][r0] = l0;
        b1h[kp][r1] = h1; b1l[kp][r1] = l1;
    }
#pragma unroll
    for (int it = 0; it < 16; it++) {
        int idx = tid + it * 128;
        int kp  = idx >> 6;
        int n   = idx & 63;
        size_t ro = (size_t)(rbase + 2 * kp) * CONVD + DINNER + n;
        float v0 = g_xBCc[ro]         * seL[2 * kp];
        float v1 = g_xBCc[ro + CONVD] * seL[2 * kp + 1];
        b2[kp][n] = packh(v0, v1);
    }
    __syncthreads();

    float yacc[8][4], sacc[8][4];
#pragma unroll
    for (int i = 0; i < 8; i++)
#pragma unroll
        for (int e = 0; e < 4; e++) { yacc[i][e] = 0.f; sacc[i][e] = 0.f; }
#pragma unroll
    for (int ks = 0; ks < 4; ks++) {
        uint32_t mh[4], ml[4], sh[4];
        mh[0] = b1h[ks*8+qid  ][r0]; mh[1] = b1h[ks*8+qid  ][r1];
        mh[2] = b1h[ks*8+qid+4][r0]; mh[3] = b1h[ks*8+qid+4][r1];
        ml[0] = b1l[ks*8+qid  ][r0]; ml[1] = b1l[ks*8+qid  ][r1];
        ml[2] = b1l[ks*8+qid+4][r0]; ml[3] = b1l[ks*8+qid+4][r1];
        sh[0] = b2[ks*8+qid  ][r0];  sh[1] = b2[ks*8+qid  ][r1];
        sh[2] = b2[ks*8+qid+4][r0];  sh[3] = b2[ks*8+qid+4][r1];
#pragma unroll
        for (int nf = 0; nf < 8; nf++) {
            int c0 = nf * 8 + grp;
            uint32_t bb[2] = { b3[ks*8+qid][c0], b3[ks*8+qid+4][c0] };
            MMA_F16(yacc[nf], mh, bb);
            MMA_F16(yacc[nf], ml, bb);
            MMA_F16(sacc[nf], sh, bb);
        }
    }

    const size_t sbase = (size_t)(bh * NCHUNK + chunk) * (64 * DSTATE);
#pragma unroll
    for (int nf = 0; nf < 8; nf++) {
        int p0 = nf * 8 + 2 * qid;
        size_t y0 = (size_t)(rbase + r0) * DINNER + h * 64 + p0;
        size_t y1 = (size_t)(rbase + r1) * DINNER + h * 64 + p0;
        g_y[y0]     = yacc[nf][0];
        g_y[y0 + 1] = yacc[nf][1];
        g_y[y1]     = yacc[nf][2];
        g_y[y1 + 1] = yacc[nf][3];
        g_state[sbase + (size_t)r0 * 64 + p0]     = sacc[nf][0];
        g_state[sbase + (size_t)r0 * 64 + p0 + 1] = sacc[nf][1];
        g_state[sbase + (size_t)r1 * 64 + p0]     = sacc[nf][2];
        g_state[sbase + (size_t)r1 * 64 + p0 + 1] = sacc[nf][3];
    }
}

// ------------------------- pass B: prefix over chunk states -------------------------
__global__ __launch_bounds__(256) void state_combine_kernel()
{
    const int bh = blockIdx.x;
    const int tid = threadIdx.x;
    const size_t base = (size_t)bh * NCHUNK * (64 * DSTATE);
    float4 hin[4];
#pragma unroll
    for (int q = 0; q < 4; q++) hin[q] = make_float4(0.f, 0.f, 0.f, 0.f);

    for (int c = 1; c < NCHUNK; c++) {
        float ap = g_acum[(size_t)bh * SEQLENN + c * NCH - 1];
        const float4* sl = (const float4*)(g_state + base + (size_t)(c - 1) * (64 * DSTATE) + tid * 16);
        float4* ho = (float4*)(g_hin + base + (size_t)c * (64 * DSTATE) + tid * 16);
#pragma unroll
        for (int q = 0; q < 4; q++) {
            float4 s = sl[q];
            hin[q].x = fmaf(hin[q].x, ap, s.x);
            hin[q].y = fmaf(hin[q].y, ap, s.y);
            hin[q].z = fmaf(hin[q].z, ap, s.z);
            hin[q].w = fmaf(hin[q].w, ap, s.w);
            ho[q] = hin[q];
        }
    }
}

// ------------------------- pass C: y += (C .* L) @ S_in^T -------------------------
__global__ __launch_bounds__(128) void carry_mma_kernel()
{
    const int bid   = blockIdx.x;
    const int chunk = 1 + (bid % (NCHUNK - 1));
    const int bh    = bid / (NCHUNK - 1);
    const int h     = bh & (NHEADSN - 1);
    const int b     = bh >> 5;
    const int tid   = threadIdx.x;
    const int warp  = tid >> 5;
    const int lane  = tid & 31;
    const int grp   = lane >> 2;
    const int qid   = lane & 3;
    const int rbase = b * SEQLENN + chunk * NCH;
    const int r0    = warp * 16 + grp;
    const int r1    = r0 + 8;

    __shared__ uint32_t ach[32][72];
    __shared__ uint32_t acl[32][72];
    __shared__ uint32_t sbb[32][72];

#pragma unroll
    for (int it = 0; it < 8; it++) {
        int idx = tid + it * 128;
        int r   = idx >> 4;
        int kk  = (idx & 15) << 2;
        float Lt = g_acum[(size_t)bh * SEQLENN + chunk * NCH + r];
        float4 cv = *(const float4*)(g_xBCc + (size_t)(rbase + r) * CONVD + DINNER + DSTATE + kk);
        cv.x *= Lt; cv.y *= Lt; cv.z *= Lt; cv.w *= Lt;
        int sp = kk >> 1;
        float e0, e1;
        ach[sp    ][r] = packh_hi(cv.x, cv.y, e0, e1); acl[sp    ][r] = packh(e0, e1);
        ach[sp + 1][r] = packh_hi(cv.z, cv.w, e0, e1); acl[sp + 1][r] = packh(e0, e1);
    }
    {
        const float* si = g_hin + (size_t)(bh * NCHUNK + chunk) * (64 * DSTATE);
#pragma unroll
        for (int it = 0; it < 16; it++) {
            int idx = tid + it * 128;
            int kp  = idx >> 6;
            int p   = idx & 63;
            float s0 = si[(size_t)(2 * kp) * 64 + p];
            float s1 = si[(size_t)(2 * kp + 1) * 64 + p];
            sbb[kp][p] = packh(s0, s1);
        }
    }
    __syncthreads();

    float yacc[8][4];
#pragma unroll
    for (int i = 0; i < 8; i++)
#pragma unroll
        for (int e = 0; e < 4; e++) yacc[i][e] = 0.f;
#pragma unroll
    for (int ks = 0; ks < 4; ks++) {
        uint32_t ah[4], al[4];
        ah[0] = ach[ks*8+qid  ][r0]; ah[1] = ach[ks*8+qid  ][r1];
        ah[2] = ach[ks*8+qid+4][r0]; ah[3] = ach[ks*8+qid+4][r1];
        al[0] = acl[ks*8+qid  ][r0]; al[1] = acl[ks*8+qid  ][r1];
        al[2] = acl[ks*8+qid+4][r0]; al[3] = acl[ks*8+qid+4][r1];
#pragma unroll
        for (int nf = 0; nf < 8; nf++) {
            int c0 = nf * 8 + grp;
            uint32_t bb[2] = { sbb[ks*8+qid][c0], sbb[ks*8+qid+4][c0] };
            MMA_F16(yacc[nf], ah, bb);
            MMA_F16(yacc[nf], al, bb);
        }
    }

#pragma unroll
    for (int nf = 0; nf < 8; nf++) {
        int p0 = nf * 8 + 2 * qid;
        size_t y0 = (size_t)(rbase + r0) * DINNER + h * 64 + p0;
        size_t y1 = (size_t)(rbase + r1) * DINNER + h * 64 + p0;
        g_y[y0]     += yacc[nf][0];
        g_y[y0 + 1] += yacc[nf][1];
        g_y[y1]     += yacc[nf][2];
        g_y[y1 + 1] += yacc[nf][3];
    }
}

// ------------------------- D*x, gate, RMSNorm -> packed fp16 -------------------------
__global__ __launch_bounds__(256) void gate_norm_kernel(
    const float* __restrict__ Dp, const float* __restrict__ norm_w)
{
    const int row = blockIdx.x;
    const int tid = threadIdx.x;
    const int c0 = tid * 8;
    const int hh = c0 >> 6;

    float vals[8];
    float ss = 0.f;
    {
        const float4* yv = (const float4*)(g_y + (size_t)row * DINNER + c0);
        const float4* xv = (const float4*)(g_xBCc + (size_t)row * CONVD + c0);
        const float4* zv = (const float4*)(g_zxbcdt + (size_t)row * ZXW + c0);
        float Dh = Dp[hh];
#pragma unroll
        for (int q = 0; q < 2; q++) {
            float4 y = yv[q], x = xv[q], z = zv[q];
            float a[4] = {y.x, y.y, y.z, y.w};
            float bb[4] = {x.x, x.y, x.z, x.w};
            float g[4] = {z.x, z.y, z.z, z.w};
#pragma unroll
            for (int e = 0; e < 4; e++) {
                float yy = fmaf(Dh, bb[e], a[e]);
                float gg = g[e] / (1.f + expf(-g[e]));
                float v = yy * gg;
                vals[q * 4 + e] = v;
                ss = fmaf(v, v, ss);
            }
        }
    }
    __shared__ float red[32];
    for (int o = 16; o; o >>= 1) ss += __shfl_down_sync(0xffffffffu, ss, o);
    if ((tid & 31) == 0) red[tid >> 5] = ss;
    __syncthreads();
    if (tid < 32) {
        float s2 = (tid < 8) ? red[tid] : 0.f;
        for (int o = 4; o; o >>= 1) s2 += __shfl_down_sync(0xffffffffu, s2, o);
        if (tid == 0) red[0] = s2;
    }
    __syncthreads();
    float scale = rsqrtf(red[0] / (float)DINNER + EPSV);

    uint32_t ho[4];
#pragma unroll
    for (int j = 0; j < 4; j++) {
        float a  = vals[2*j]     * scale * norm_w[c0 + 2*j];
        float bv = vals[2*j + 1] * scale * norm_w[c0 + 2*j + 1];
        ho[j] = packh(a, bv);
    }
    *(uint4*)(g_ynh + (size_t)row * (DINNER/2) + tid * 4) = *(uint4*)ho;
}

// ------------------------- launch -------------------------
extern "C" void kernel_launch(void* const* d_in, const int* in_sizes, int n_in,
                              void* d_out, int out_size)
{
    const float* X          = (const float*)d_in[0];
    const float* in_proj_w  = (const float*)d_in[1];
    const float* conv_w     = (const float*)d_in[2];
    const float* conv_b     = (const float*)d_in[3];
    const float* dt_bias    = (const float*)d_in[4];
    const float* A_log      = (const float*)d_in[5];
    const float* Dp         = (const float*)d_in[6];
    const float* norm_w     = (const float*)d_in[7];
    const float* out_proj_w = (const float*)d_in[8];
    const float* to_h_w     = (const float*)d_in[9];
    float* out = (float*)d_out;

    float *zx;
    uint32_t *Xh, *Wih, *Woh, *Wth, *ynh, *Hh;
    cudaGetSymbolAddress((void**)&zx,  g_zxbcdt);
    cudaGetSymbolAddress((void**)&Xh,  g_Xh);
    cudaGetSymbolAddress((void**)&Wih, g_Wih);
    cudaGetSymbolAddress((void**)&Woh, g_Woh);
    cudaGetSymbolAddress((void**)&Wth, g_Wth);
    cudaGetSymbolAddress((void**)&ynh, g_ynh);
    cudaGetSymbolAddress((void**)&Hh,  g_Hh);

    // 0) pack all operands to fp16 (single launch)
    pack_all_kernel<<<(PN1 + PN2 + PN3 + PN4 + 255) / 256, 256>>>(X, in_proj_w, out_proj_w, to_h_w);

    // 1) z|xBC = X @ in_proj_w[0:4224]^T  (pure fp16, 128x128 tiles)
    gemm_f16<0><<<dim3(ZXW / 128, NROWS / 128), 256>>>(
        Xh, Wih, zx, nullptr, NROWS, ZXW, DIMN);
    // 2) dt = softplus(X . Wi_dt + bias)  (fp32 exact)
    dt_gemv_kernel<<<NROWS, 256>>>(X, in_proj_w, dt_bias);
    // 3) conv + silu (tiled)
    conv_silu_kernel<<<((NROWS / 4) * (CONVD / 4) + 255) / 256, 256>>>(conv_w, conv_b);
    // 4) chunked SSD scan: local MMA pass, state prefix, carry MMA
    scan_chunk_kernel<<<BATCHN * NHEADSN * NCHUNK, 128>>>(A_log);
    state_combine_kernel<<<BATCHN * NHEADSN, 256>>>();
    carry_mma_kernel<<<BATCHN * NHEADSN * (NCHUNK - 1), 128>>>();
    // 5) gate + rmsnorm -> packed fp16 yn
    gate_norm_kernel<<<NROWS, 256>>>(Dp, norm_w);
    // 6) H = yn @ out_proj_w^T  (pure fp16, packed out)
    gemm_f16<1><<<dim3(DIMN / 128, NROWS / 128), 256>>>(
        ynh, Woh, nullptr, Hh, NROWS, DIMN, DINNER);
    // 7) HKV = H @ to_h_w^T with fused split  (pure fp16)
    gemm_f16<2><<<dim3(DINNER / 128, NROWS / 128), 256>>>(
        Hh, Wth, out, nullptr, NROWS, DINNER, DIMN);
}

// round 17
// speedup vs baseline: 1.0732x; 1.0304x over previous
#include <cuda_runtime.h>
#include <cuda_fp16.h>
#include <math.h>
#include <stdint.h>

#define BATCHN 2
#define SEQLENN 4096
#define DIMN 1024
#define DSTATE 64
#define DCONVN 4
#define DINNER 2048
#define NHEADSN 32
#define CONVD 2176          // D_INNER + 2*D_STATE
#define ZXW 4224            // z + xBC columns (dt handled separately); 33*128
#define NROWS (BATCHN*SEQLENN)   // 8192
#define NCH 64              // timesteps per chunk
#define NCHUNK (SEQLENN/NCH)    // 64
#define EPSV 1e-5f

// ------------------------- scratch -------------------------
__device__ float g_zxbcdt[(size_t)NROWS * ZXW];     // z | xBC
__device__ float g_xBCc[(size_t)NROWS * CONVD];
__device__ float g_dt[(size_t)NROWS * NHEADSN];
__device__ float g_y[(size_t)NROWS * DINNER];
__device__ float g_state[(size_t)BATCHN * NHEADSN * NCHUNK * DSTATE * 64];
__device__ float g_hin[(size_t)BATCHN * NHEADSN * NCHUNK * DSTATE * 64];
__device__ float g_acum[(size_t)BATCHN * NHEADSN * SEQLENN];

// packed fp16 operands (uint32 = 2 halves along K)
__device__ uint32_t g_Xh[(size_t)NROWS * (DIMN/2)];
__device__ uint32_t g_Wih[(size_t)ZXW * (DIMN/2)];
__device__ uint32_t g_Woh[(size_t)DIMN * (DINNER/2)];
__device__ uint32_t g_Wth[(size_t)DINNER * (DIMN/2)];
__device__ uint32_t g_ynh[(size_t)NROWS * (DINNER/2)];
__device__ uint32_t g_Hh[(size_t)NROWS * (DIMN/2)];

// ------------------------- fp16 helpers -------------------------
__device__ __forceinline__ uint32_t packh_hi(float a, float b, float& ra, float& rb) {
    __half2 h = __floats2half2_rn(a, b);
    ra = a - __half2float(__low2half(h));
    rb = b - __half2float(__high2half(h));
    return *(uint32_t*)&h;
}
__device__ __forceinline__ uint32_t packh(float a, float b) {
    __half2 h = __floats2half2_rn(a, b);
    return *(uint32_t*)&h;
}

#define MMA_F16(c, a, b) \
    asm volatile("mma.sync.aligned.m16n8k16.row.col.f32.f16.f16.f32 " \
        "{%0,%1,%2,%3}, {%4,%5,%6,%7}, {%8,%9}, {%0,%1,%2,%3};" \
        : "+f"((c)[0]), "+f"((c)[1]), "+f"((c)[2]), "+f"((c)[3]) \
        : "r"((a)[0]), "r"((a)[1]), "r"((a)[2]), "r"((a)[3]), \
          "r"((b)[0]), "r"((b)[1]))

// ------------------------- pure fp16 GEMM: C[M,N] = Ah[M,K] @ Bh[N,K]^T (proven) -------------------------
template<int MODE>
__global__ __launch_bounds__(256) void gemm_f16(
    const uint32_t* __restrict__ Ahg, const uint32_t* __restrict__ Bhg,
    float* __restrict__ Cf, uint32_t* __restrict__ Ch,
    int M, int N, int K)
{
    __shared__ uint32_t Ah[8][136];
    __shared__ uint32_t Bh[8][136];

    const int tid  = threadIdx.x;
    const int bm   = blockIdx.y * 128;
    const int bn   = blockIdx.x * 128;
    const int lane = tid & 31;
    const int warp = tid >> 5;
    const int wm   = (warp >> 2) * 64;
    const int wn   = (warp & 3) * 32;
    const int grp  = lane >> 2;
    const int qid  = lane & 3;
    const int K2   = K >> 1;

    const int sr = tid >> 1;
    const int sc = (tid & 1) * 4;
    const size_t aoff = (size_t)(bm + sr) * K2 + sc;
    const size_t boff = (size_t)(bn + sr) * K2 + sc;

    float acc[4][4][4];
#pragma unroll
    for (int i = 0; i < 4; i++)
#pragma unroll
        for (int j = 0; j < 4; j++)
#pragma unroll
            for (int e = 0; e < 4; e++) acc[i][j][e] = 0.f;

    uint4 avh = *(const uint4*)(Ahg + aoff);
    uint4 bvh = *(const uint4*)(Bhg + boff);

    for (int kb = 0; kb < K2; kb += 8) {
        Ah[sc + 0][sr] = avh.x; Ah[sc + 1][sr] = avh.y;
        Ah[sc + 2][sr] = avh.z; Ah[sc + 3][sr] = avh.w;
        Bh[sc + 0][sr] = bvh.x; Bh[sc + 1][sr] = bvh.y;
        Bh[sc + 2][sr] = bvh.z; Bh[sc + 3][sr] = bvh.w;
        __syncthreads();

        if (kb + 8 < K2) {
            avh = *(const uint4*)(Ahg + aoff + kb + 8);
            bvh = *(const uint4*)(Bhg + boff + kb + 8);
        }

        uint32_t ah[4][4];
#pragma unroll
        for (int mf = 0; mf < 4; mf++) {
            int r0 = wm + mf * 16 + grp;
            ah[mf][0] = Ah[qid    ][r0];
            ah[mf][1] = Ah[qid    ][r0 + 8];
            ah[mf][2] = Ah[qid + 4][r0];
            ah[mf][3] = Ah[qid + 4][r0 + 8];
        }
        uint32_t bh[4][2];
#pragma unroll
        for (int nf = 0; nf < 4; nf++) {
            int c0 = wn + nf * 8 + grp;
            bh[nf][0] = Bh[qid    ][c0];
            bh[nf][1] = Bh[qid + 4][c0];
        }
#pragma unroll
        for (int mf = 0; mf < 4; mf++)
#pragma unroll
            for (int nf = 0; nf < 4; nf++)
                MMA_F16(acc[mf][nf], ah[mf], bh[nf]);
        __syncthreads();
    }

#pragma unroll
    for (int mf = 0; mf < 4; mf++) {
        int gr0 = bm + wm + mf * 16 + grp;
        int gr1 = gr0 + 8;
#pragma unroll
        for (int nf = 0; nf < 4; nf++) {
            int gc = bn + wn + nf * 8 + 2 * qid;
            if (MODE == 0) {
                Cf[(size_t)gr0 * N + gc]     = acc[mf][nf][0];
                Cf[(size_t)gr0 * N + gc + 1] = acc[mf][nf][1];
                Cf[(size_t)gr1 * N + gc]     = acc[mf][nf][2];
                Cf[(size_t)gr1 * N + gc + 1] = acc[mf][nf][3];
            } else if (MODE == 1) {
                int kp = gc >> 1;
                Ch[(size_t)gr0 * (N/2) + kp] = packh(acc[mf][nf][0], acc[mf][nf][1]);
                Ch[(size_t)gr1 * (N/2) + kp] = packh(acc[mf][nf][2], acc[mf][nf][3]);
            } else {
                size_t off = (gc < DIMN)
                    ? (size_t)gr0 * DIMN + gc
                    : (size_t)NROWS * DIMN + (size_t)gr0 * DIMN + (gc - DIMN);
                Cf[off]     = acc[mf][nf][0];
                Cf[off + 1] = acc[mf][nf][1];
                size_t off1 = off + (size_t)8 * DIMN;
                Cf[off1]     = acc[mf][nf][2];
                Cf[off1 + 1] = acc[mf][nf][3];
            }
        }
    }
}

// ------------------------- merged pack kernel -------------------------
#define PN1 (NROWS * DIMN / 4)
#define PN2 (ZXW * DIMN / 4)
#define PN3 (DIMN * DINNER / 4)
#define PN4 (DINNER * DIMN / 4)
__global__ void pack_all_kernel(const float* __restrict__ X, const float* __restrict__ Wi,
                                const float* __restrict__ Wo, const float* __restrict__ Wt)
{
    int i = blockIdx.x * blockDim.x + threadIdx.x;
    const float* src;
    uint32_t* dst;
    int j = i;
    if (j < PN1) { src = X; dst = g_Xh; }
    else if ((j -= PN1) < PN2) { src = Wi; dst = g_Wih; }
    else if ((j -= PN2) < PN3) { src = Wo; dst = g_Woh; }
    else if ((j -= PN3) < PN4) { src = Wt; dst = g_Wth; }
    else return;
    float4 v = ((const float4*)src)[j];
    ((uint2*)dst)[j] = make_uint2(packh(v.x, v.y), packh(v.z, v.w));
}

// ------------------------- dt GEMV (fp32 exact) + softplus -------------------------
__global__ __launch_bounds__(256) void dt_gemv_kernel(
    const float* __restrict__ X, const float* __restrict__ Wi, const float* __restrict__ dt_bias)
{
    const int row  = blockIdx.x;
    const int tid  = threadIdx.x;
    const int warp = tid >> 5;
    const int lane = tid & 31;
    __shared__ __align__(16) float sx[DIMN];
    *(float4*)&sx[tid * 4] = *(const float4*)(X + (size_t)row * DIMN + tid * 4);
    __syncthreads();
#pragma unroll
    for (int hh = 0; hh < 4; hh++) {
        int h = warp * 4 + hh;
        const float* w = Wi + (size_t)(ZXW + h) * DIMN;
        float s = 0.f;
#pragma unroll
        for (int i = 0; i < 8; i++) {
            int k = (lane + i * 32) * 4;
            float4 xv = *(const float4*)&sx[k];
            float4 wv = *(const float4*)(w + k);
            s = fmaf(xv.x, wv.x, s); s = fmaf(xv.y, wv.y, s);
            s = fmaf(xv.z, wv.z, s); s = fmaf(xv.w, wv.w, s);
        }
        for (int o = 16; o; o >>= 1) s += __shfl_down_sync(0xffffffffu, s, o);
        if (lane == 0) {
            float v = s + dt_bias[h];
            g_dt[(size_t)row * NHEADSN + h] = (v > 20.f) ? v : log1pf(expf(v));
        }
    }
}

// ------------------------- depthwise causal conv (w=4) + bias + SiLU, tiled -------------------------
__global__ __launch_bounds__(256) void conv_silu_kernel(
    const float* __restrict__ cw, const float* __restrict__ cb)
{
    const int idx = blockIdx.x * 256 + threadIdx.x;
    const int CG = CONVD / 4;          // 544
    if (idx >= (NROWS / 4) * CG) return;
    const int cg = idx % CG;
    const int tg = idx / CG;
    const int c0 = cg * 4;
    const int l0 = (tg & (SEQLENN / 4 - 1)) * 4;
    const int b  = tg >> 10;

    const float* src = g_zxbcdt + DINNER + c0;
    const float4 z4 = make_float4(0.f, 0.f, 0.f, 0.f);
    float4 in[7];
#pragma unroll
    for (int j = 0; j < 7; j++) {
        int lt = l0 + j - 3;
        in[j] = (lt >= 0) ? *(const float4*)(src + (size_t)(b * SEQLENN + lt) * ZXW) : z4;
    }
    float4 w0 = *(const float4*)(cw + (c0 + 0) * 4);
    float4 w1 = *(const float4*)(cw + (c0 + 1) * 4);
    float4 w2 = *(const float4*)(cw + (c0 + 2) * 4);
    float4 w3 = *(const float4*)(cw + (c0 + 3) * 4);
    float4 bias = *(const float4*)(cb + c0);

#pragma unroll
    for (int t = 0; t < 4; t++) {
        float ox = bias.x, oy = bias.y, oz = bias.z, ow = bias.w;
        ox = fmaf(w0.x, in[t].x, ox); ox = fmaf(w0.y, in[t+1].x, ox);
        ox = fmaf(w0.z, in[t+2].x, ox); ox = fmaf(w0.w, in[t+3].x, ox);
        oy = fmaf(w1.x, in[t].y, oy); oy = fmaf(w1.y, in[t+1].y, oy);
        oy = fmaf(w1.z, in[t+2].y, oy); oy = fmaf(w1.w, in[t+3].y, oy);
        oz = fmaf(w2.x, in[t].z, oz); oz = fmaf(w2.y, in[t+1].z, oz);
        oz = fmaf(w2.z, in[t+2].z, oz); oz = fmaf(w2.w, in[t+3].z, oz);
        ow = fmaf(w3.x, in[t].w, ow); ow = fmaf(w3.y, in[t+1].w, ow);
        ow = fmaf(w3.z, in[t+2].w, ow); ow = fmaf(w3.w, in[t+3].w, ow);
        float4 o;
        o.x = ox / (1.f + expf(-ox));
        o.y = oy / (1.f + expf(-oy));
        o.z = oz / (1.f + expf(-oz));
        o.w = ow / (1.f + expf(-ow));
        *(float4*)(g_xBCc + (size_t)(b * SEQLENN + l0 + t) * CONVD + c0) = o;
    }
}

// ------------------------- pass A': per-chunk states S = (B .* eL)^T @ Xd -------------------------
__global__ __launch_bounds__(128) void state_chunk_kernel(const float* __restrict__ A_log)
{
    const int bid   = blockIdx.x;
    const int chunk = bid & (NCHUNK - 1);
    const int h     = (bid >> 6) & (NHEADSN - 1);
    const int b     = bid >> 11;
    const int tid   = threadIdx.x;
    const int warp  = tid >> 5;
    const int lane  = tid & 31;
    const int grp   = lane >> 2;
    const int qid   = lane & 3;
    const float Ahc = -expf(A_log[h]);
    const int bh    = b * NHEADSN + h;
    const int rbase = b * SEQLENN + chunk * NCH;
    const int r0    = warp * 16 + grp;
    const int r1    = r0 + 8;

    __shared__ uint32_t b2[32][72];    // Bd [kp s][n]
    __shared__ uint32_t b3[32][72];    // Xd [kp s][p]
    __shared__ float sdt[NCH], scum[NCH], seL[NCH];

    if (tid < NCH) sdt[tid] = g_dt[(size_t)(rbase + tid) * NHEADSN + h];
    __syncthreads();
    if (tid == 0) {
        float c = 0.f;
#pragma unroll
        for (int t = 0; t < NCH; t++) { c += sdt[t] * Ahc; scum[t] = c; }
    }
    __syncthreads();
    if (tid < NCH) {
        seL[tid] = __expf(scum[NCH - 1] - scum[tid]);
        g_acum[(size_t)bh * SEQLENN + chunk * NCH + tid] = __expf(scum[tid]);
    }
    __syncthreads();
#pragma unroll
    for (int it = 0; it < 16; it++) {
        int idx = tid + it * 128;
        int kp  = idx >> 6;
        int n   = idx & 63;
        size_t ro = (size_t)(rbase + 2 * kp) * CONVD + DINNER + n;
        float v0 = g_xBCc[ro]         * seL[2 * kp];
        float v1 = g_xBCc[ro + CONVD] * seL[2 * kp + 1];
        b2[kp][n] = packh(v0, v1);
        size_t rx = (size_t)(rbase + 2 * kp) * CONVD + h * 64 + n;
        float x0 = g_xBCc[rx]         * sdt[2 * kp];
        float x1 = g_xBCc[rx + CONVD] * sdt[2 * kp + 1];
        b3[kp][n] = packh(x0, x1);
    }
    __syncthreads();

    float sacc[8][4];
#pragma unroll
    for (int i = 0; i < 8; i++)
#pragma unroll
        for (int e = 0; e < 4; e++) sacc[i][e] = 0.f;
#pragma unroll
    for (int ks = 0; ks < 4; ks++) {
        uint32_t sh[4];
        sh[0] = b2[ks*8+qid  ][r0]; sh[1] = b2[ks*8+qid  ][r1];
        sh[2] = b2[ks*8+qid+4][r0]; sh[3] = b2[ks*8+qid+4][r1];
#pragma unroll
        for (int nf = 0; nf < 8; nf++) {
            int c0 = nf * 8 + grp;
            uint32_t bb[2] = { b3[ks*8+qid][c0], b3[ks*8+qid+4][c0] };
            MMA_F16(sacc[nf], sh, bb);
        }
    }

    const size_t sbase = (size_t)(bh * NCHUNK + chunk) * (64 * DSTATE);
#pragma unroll
    for (int nf = 0; nf < 8; nf++) {
        int p0 = nf * 8 + 2 * qid;
        g_state[sbase + (size_t)r0 * 64 + p0]     = sacc[nf][0];
        g_state[sbase + (size_t)r0 * 64 + p0 + 1] = sacc[nf][1];
        g_state[sbase + (size_t)r1 * 64 + p0]     = sacc[nf][2];
        g_state[sbase + (size_t)r1 * 64 + p0 + 1] = sacc[nf][3];
    }
}

// ------------------------- pass B: prefix over chunk states -------------------------
__global__ __launch_bounds__(256) void state_combine_kernel()
{
    const int bh = blockIdx.x;
    const int tid = threadIdx.x;
    const size_t base = (size_t)bh * NCHUNK * (64 * DSTATE);
    float4 hin[4];
#pragma unroll
    for (int q = 0; q < 4; q++) hin[q] = make_float4(0.f, 0.f, 0.f, 0.f);

    for (int c = 1; c < NCHUNK; c++) {
        float ap = g_acum[(size_t)bh * SEQLENN + c * NCH - 1];
        const float4* sl = (const float4*)(g_state + base + (size_t)(c - 1) * (64 * DSTATE) + tid * 16);
        float4* ho = (float4*)(g_hin + base + (size_t)c * (64 * DSTATE) + tid * 16);
#pragma unroll
        for (int q = 0; q < 4; q++) {
            float4 s = sl[q];
            hin[q].x = fmaf(hin[q].x, ap, s.x);
            hin[q].y = fmaf(hin[q].y, ap, s.y);
            hin[q].z = fmaf(hin[q].z, ap, s.z);
            hin[q].w = fmaf(hin[q].w, ap, s.w);
            ho[q] = hin[q];
        }
    }
}

// ------------------------- pass C': full y = M@Xd + L .* (C @ S_in^T) -------------------------
__global__ __launch_bounds__(128) void y_chunk_kernel(const float* __restrict__ A_log)
{
    const int bid   = blockIdx.x;
    const int chunk = bid & (NCHUNK - 1);
    const int h     = (bid >> 6) & (NHEADSN - 1);
    const int b     = bid >> 11;
    const int tid   = threadIdx.x;
    const int warp  = tid >> 5;
    const int lane  = tid & 31;
    const int grp   = lane >> 2;
    const int qid   = lane & 3;
    const float Ahc = -expf(A_log[h]);
    const int bh    = b * NHEADSN + h;
    const int rbase = b * SEQLENN + chunk * NCH;
    const int r0    = warp * 16 + grp;
    const int r1    = r0 + 8;

    __shared__ uint32_t b1h[32][72];   // C hi -> M hi  [kp][row]
    __shared__ uint32_t b1l[32][72];   // C lo -> M lo
    __shared__ uint32_t b2[32][72];    // B -> S_in
    __shared__ uint32_t b3[32][72];    // Xd
    __shared__ float sdt[NCH], scum[NCH];

    if (tid < NCH) sdt[tid] = g_dt[(size_t)(rbase + tid) * NHEADSN + h];
#pragma unroll
    for (int it = 0; it < 8; it++) {
        int idx = tid + it * 128;
        int r   = idx >> 4;
        int kk  = (idx & 15) << 2;
        size_t ro = (size_t)(rbase + r) * CONVD + DINNER;
        float4 bv = *(const float4*)(g_xBCc + ro + kk);
        float4 cv = *(const float4*)(g_xBCc + ro + DSTATE + kk);
        int sp = kk >> 1;
        float e0, e1;
        b1h[sp    ][r] = packh_hi(cv.x, cv.y, e0, e1); b1l[sp    ][r] = packh(e0, e1);
        b1h[sp + 1][r] = packh_hi(cv.z, cv.w, e0, e1); b1l[sp + 1][r] = packh(e0, e1);
        b2[sp    ][r] = packh(bv.x, bv.y);
        b2[sp + 1][r] = packh(bv.z, bv.w);
    }
    __syncthreads();
    if (tid == 0) {
        float c = 0.f;
#pragma unroll
        for (int t = 0; t < NCH; t++) { c += sdt[t] * Ahc; scum[t] = c; }
    }
    __syncthreads();

    // G = C @ B^T
    float gacc[8][4];
#pragma unroll
    for (int i = 0; i < 8; i++)
#pragma unroll
        for (int e = 0; e < 4; e++) gacc[i][e] = 0.f;
#pragma unroll
    for (int ks = 0; ks < 4; ks++) {
        uint32_t ah[4], al[4];
        ah[0] = b1h[ks*8+qid  ][r0]; ah[1] = b1h[ks*8+qid  ][r1];
        ah[2] = b1h[ks*8+qid+4][r0]; ah[3] = b1h[ks*8+qid+4][r1];
        al[0] = b1l[ks*8+qid  ][r0]; al[1] = b1l[ks*8+qid  ][r1];
        al[2] = b1l[ks*8+qid+4][r0]; al[3] = b1l[ks*8+qid+4][r1];
#pragma unroll
        for (int nf = 0; nf < 8; nf++) {
            int c0 = nf * 8 + grp;
            uint32_t bb[2] = { b2[ks*8+qid][c0], b2[ks*8+qid+4][c0] };
            MMA_F16(gacc[nf], ah, bb);
            MMA_F16(gacc[nf], al, bb);
        }
    }
    __syncthreads();

    // restage: b2 <- S_in [kp n][p] (zeros for chunk 0), b3 <- Xd [kp s][p]
    {
        const float* si = g_hin + (size_t)(bh * NCHUNK + chunk) * (64 * DSTATE);
#pragma unroll
        for (int it = 0; it < 16; it++) {
            int idx = tid + it * 128;
            int kp  = idx >> 6;
            int p   = idx & 63;
            if (chunk > 0) {
                float s0 = si[(size_t)(2 * kp) * 64 + p];
                float s1 = si[(size_t)(2 * kp + 1) * 64 + p];
                b2[kp][p] = packh(s0, s1);
            } else {
                b2[kp][p] = 0u;
            }
            size_t rx = (size_t)(rbase + 2 * kp) * CONVD + h * 64 + p;
            float x0 = g_xBCc[rx]         * sdt[2 * kp];
            float x1 = g_xBCc[rx + CONVD] * sdt[2 * kp + 1];
            b3[kp][p] = packh(x0, x1);
        }
    }
    __syncthreads();

    // carry: cacc = C @ S_in^T  (b1 still holds C)
    float cacc[8][4];
#pragma unroll
    for (int i = 0; i < 8; i++)
#pragma unroll
        for (int e = 0; e < 4; e++) cacc[i][e] = 0.f;
#pragma unroll
    for (int ks = 0; ks < 4; ks++) {
        uint32_t ah[4], al[4];
        ah[0] = b1h[ks*8+qid  ][r0]; ah[1] = b1h[ks*8+qid  ][r1];
        ah[2] = b1h[ks*8+qid+4][r0]; ah[3] = b1h[ks*8+qid+4][r1];
        al[0] = b1l[ks*8+qid  ][r0]; al[1] = b1l[ks*8+qid  ][r1];
        al[2] = b1l[ks*8+qid+4][r0]; al[3] = b1l[ks*8+qid+4][r1];
#pragma unroll
        for (int nf = 0; nf < 8; nf++) {
            int c0 = nf * 8 + grp;
            uint32_t bb[2] = { b2[ks*8+qid][c0], b2[ks*8+qid+4][c0] };
            MMA_F16(cacc[nf], ah, bb);
            MMA_F16(cacc[nf], al, bb);
        }
    }

    // pack M = tril(G * exp(cum_t - cum_s)) into b1 (warp-local rows; no barrier needed)
#pragma unroll
    for (int nf = 0; nf < 8; nf++) {
        int s0 = nf * 8 + 2 * qid;
        float m0 = (s0     <= r0) ? gacc[nf][0] * __expf(scum[r0] - scum[s0    ]) : 0.f;
        float m1 = (s0 + 1 <= r0) ? gacc[nf][1] * __expf(scum[r0] - scum[s0 + 1]) : 0.f;
        float m2 = (s0     <= r1) ? gacc[nf][2] * __expf(scum[r1] - scum[s0    ]) : 0.f;
        float m3 = (s0 + 1 <= r1) ? gacc[nf][3] * __expf(scum[r1] - scum[s0 + 1]) : 0.f;
        int kp = nf * 4 + qid;
        float e0, e1;
        uint32_t h0 = packh_hi(m0, m1, e0, e1); uint32_t l0 = packh(e0, e1);
        uint32_t h1 = packh_hi(m2, m3, e0, e1); uint32_t l1 = packh(e0, e1);
        b1h[kp][r0] = h0; b1l[kp][r0] = l0;
        b1h[kp][r1] = h1; b1l[kp][r1] = l1;
    }

    // Y = M @ Xd
    float yacc[8][4];
#pragma unroll
    for (int i = 0; i < 8; i++)
#pragma unroll
        for (int e = 0; e < 4; e++) yacc[i][e] = 0.f;
#pragma unroll
    for (int ks = 0; ks < 4; ks++) {
        uint32_t mh[4], ml[4];
        mh[0] = b1h[ks*8+qid  ][r0]; mh[1] = b1h[ks*8+qid  ][r1];
        mh[2] = b1h[ks*8+qid+4][r0]; mh[3] = b1h[ks*8+qid+4][r1];
        ml[0] = b1l[ks*8+qid  ][r0]; ml[1] = b1l[ks*8+qid  ][r1];
        ml[2] = b1l[ks*8+qid+4][r0]; ml[3] = b1l[ks*8+qid+4][r1];
#pragma unroll
        for (int nf = 0; nf < 8; nf++) {
            int c0 = nf * 8 + grp;
            uint32_t bb[2] = { b3[ks*8+qid][c0], b3[ks*8+qid+4][c0] };
            MMA_F16(yacc[nf], mh, bb);
            MMA_F16(yacc[nf], ml, bb);
        }
    }

    const float L0 = __expf(scum[r0]);
    const float L1 = __expf(scum[r1]);
#pragma unroll
    for (int nf = 0; nf < 8; nf++) {
        int p0 = nf * 8 + 2 * qid;
        size_t y0 = (size_t)(rbase + r0) * DINNER + h * 64 + p0;
        size_t y1 = (size_t)(rbase + r1) * DINNER + h * 64 + p0;
        g_y[y0]     = fmaf(L0, cacc[nf][0], yacc[nf][0]);
        g_y[y0 + 1] = fmaf(L0, cacc[nf][1], yacc[nf][1]);
        g_y[y1]     = fmaf(L1, cacc[nf][2], yacc[nf][2]);
        g_y[y1 + 1] = fmaf(L1, cacc[nf][3], yacc[nf][3]);
    }
}

// ------------------------- D*x, gate, RMSNorm -> packed fp16 -------------------------
__global__ __launch_bounds__(256) void gate_norm_kernel(
    const float* __restrict__ Dp, const float* __restrict__ norm_w)
{
    const int row = blockIdx.x;
    const int tid = threadIdx.x;
    const int c0 = tid * 8;
    const int hh = c0 >> 6;

    float vals[8];
    float ss = 0.f;
    {
        const float4* yv = (const float4*)(g_y + (size_t)row * DINNER + c0);
        const float4* xv = (const float4*)(g_xBCc + (size_t)row * CONVD + c0);
        const float4* zv = (const float4*)(g_zxbcdt + (size_t)row * ZXW + c0);
        float Dh = Dp[hh];
#pragma unroll
        for (int q = 0; q < 2; q++) {
            float4 y = yv[q], x = xv[q], z = zv[q];
            float a[4] = {y.x, y.y, y.z, y.w};
            float bb[4] = {x.x, x.y, x.z, x.w};
            float g[4] = {z.x, z.y, z.z, z.w};
#pragma unroll
            for (int e = 0; e < 4; e++) {
                float yy = fmaf(Dh, bb[e], a[e]);
                float gg = g[e] / (1.f + expf(-g[e]));
                float v = yy * gg;
                vals[q * 4 + e] = v;
                ss = fmaf(v, v, ss);
            }
        }
    }
    __shared__ float red[32];
    for (int o = 16; o; o >>= 1) ss += __shfl_down_sync(0xffffffffu, ss, o);
    if ((tid & 31) == 0) red[tid >> 5] = ss;
    __syncthreads();
    if (tid < 32) {
        float s2 = (tid < 8) ? red[tid] : 0.f;
        for (int o = 4; o; o >>= 1) s2 += __shfl_down_sync(0xffffffffu, s2, o);
        if (tid == 0) red[0] = s2;
    }
    __syncthreads();
    float scale = rsqrtf(red[0] / (float)DINNER + EPSV);

    uint32_t ho[4];
#pragma unroll
    for (int j = 0; j < 4; j++) {
        float a  = vals[2*j]     * scale * norm_w[c0 + 2*j];
        float bv = vals[2*j + 1] * scale * norm_w[c0 + 2*j + 1];
        ho[j] = packh(a, bv);
    }
    *(uint4*)(g_ynh + (size_t)row * (DINNER/2) + tid * 4) = *(uint4*)ho;
}

// ------------------------- launch -------------------------
extern "C" void kernel_launch(void* const* d_in, const int* in_sizes, int n_in,
                              void* d_out, int out_size)
{
    const float* X          = (const float*)d_in[0];
    const float* in_proj_w  = (const float*)d_in[1];
    const float* conv_w     = (const float*)d_in[2];
    const float* conv_b     = (const float*)d_in[3];
    const float* dt_bias    = (const float*)d_in[4];
    const float* A_log      = (const float*)d_in[5];
    const float* Dp         = (const float*)d_in[6];
    const float* norm_w     = (const float*)d_in[7];
    const float* out_proj_w = (const float*)d_in[8];
    const float* to_h_w     = (const float*)d_in[9];
    float* out = (float*)d_out;

    float *zx;
    uint32_t *Xh, *Wih, *Woh, *Wth, *ynh, *Hh;
    cudaGetSymbolAddress((void**)&zx,  g_zxbcdt);
    cudaGetSymbolAddress((void**)&Xh,  g_Xh);
    cudaGetSymbolAddress((void**)&Wih, g_Wih);
    cudaGetSymbolAddress((void**)&Woh, g_Woh);
    cudaGetSymbolAddress((void**)&Wth, g_Wth);
    cudaGetSymbolAddress((void**)&ynh, g_ynh);
    cudaGetSymbolAddress((void**)&Hh,  g_Hh);

    // 0) pack all operands to fp16 (single launch)
    pack_all_kernel<<<(PN1 + PN2 + PN3 + PN4 + 255) / 256, 256>>>(X, in_proj_w, out_proj_w, to_h_w);

    // 1) z|xBC = X @ in_proj_w[0:4224]^T
    gemm_f16<0><<<dim3(ZXW / 128, NROWS / 128), 256>>>(
        Xh, Wih, zx, nullptr, NROWS, ZXW, DIMN);
    // 2) dt = softplus(X . Wi_dt + bias)  (fp32 exact)
    dt_gemv_kernel<<<NROWS, 256>>>(X, in_proj_w, dt_bias);
    // 3) conv + silu
    conv_silu_kernel<<<((NROWS / 4) * (CONVD / 4) + 255) / 256, 256>>>(conv_w, conv_b);
    // 4) chunked SSD scan: states, prefix, full-y
    state_chunk_kernel<<<BATCHN * NHEADSN * NCHUNK, 128>>>(A_log);
    state_combine_kernel<<<BATCHN * NHEADSN, 256>>>();
    y_chunk_kernel<<<BATCHN * NHEADSN * NCHUNK, 128>>>(A_log);
    // 5) gate + rmsnorm -> packed fp16 yn
    gate_norm_kernel<<<NROWS, 256>>>(Dp, norm_w);
    // 6) H = yn @ out_proj_w^T
    gemm_f16<1><<<dim3(DIMN / 128, NROWS / 128), 256>>>(
        ynh, Woh, nullptr, Hh, NROWS, DIMN, DINNER);
    // 7) HKV = H @ to_h_w^T with fused split
    gemm_f16<2><<<dim3(DINNER / 128, NROWS / 128), 256>>>(
        Hh, Wth, out, nullptr, NROWS, DINNER, DIMN);
}